// round 7
// baseline (speedup 1.0000x reference)
#include <cuda_runtime.h>
#include <cuda_bf16.h>
#include <stdint.h>

#define NB 2
#define NH 48
#define NW 48
#define ND 24
#define NA 9
#define NK 20
#define TOTAL  497664            // NH*NW*ND*NA
#define HWD    55296             // NH*NW*ND
#define OUTTOT 995328            // NB*NA*HWD
#define NUMFG 128
#define RPNB  256
#define NBINS 65536
#define CAP   4096

#define G2   296                 // grid size (2 per SM on 148 SMs)
#define HG   148                 // blocks per batch
#define STR  (HG * 256)          // per-batch stride   = 37888
#define STRF (G2 * 256)          // full-grid stride   = 75776
#define NIT  14                  // ceil(TOTAL / STR)
#define NITC 14                  // ceil(NB*TOTAL / STRF)
#define NITE 4                   // ceil(OUTTOT/4 / STRF)

#define OFF_BT  995328
#define OFF_IW  (OFF_BT + 5971968)
#define OFF_OW  (OFF_IW + 5971968)

// ---------------- device scratch (zero-initialized at load; reset by bar4 leader) --
__device__ int                g_ctr[5];
__device__ int                g_rel[5];
__device__ float              g_bmax[G2 * NK];      // per-block gt maxima (plain stores)
__device__ float              g_gm[NB * NK];        // adjusted gt_max
__device__ float              g_gtd[NB * NK * 6];   // gcx gcy gcz log(gw) log(gh) log(gd)
__device__ float              g_ancd[NA * 9];       // cx cy cz 1/ew 1/eh 1/ed lew leh led
__device__ signed char        g_label[NB * TOTAL];
__device__ unsigned char      g_amax[NB * TOTAL];
__device__ int                g_cnt[4];
__device__ unsigned int       g_hist[4 * NBINS];
__device__ unsigned int       g_csum[64];
__device__ unsigned int       g_bin[4];
__device__ int                g_m[4];
__device__ int                g_act[4];             // reset to 1 each run
__device__ int                g_ncand[4];
__device__ unsigned long long g_cand[4 * CAP];
__device__ unsigned long long g_thresh[4];
__device__ float              g_wval;
__device__ int                g_first = 1;          // first-run flag: act needs init 1

// IoU with strict _rn intrinsics so phase A and phase B are bitwise identical.
__device__ __forceinline__ float f_ov(float ax1, float ay1, float ax2, float ay2,
                                      float az1, float az2, float aarea,
                                      const float* __restrict__ g) {
    float iw = __fadd_rn(__fsub_rn(fminf(ax2, g[2]), fmaxf(ax1, g[0])), 1.0f);
    if (iw <= 0.0f) return 0.0f;
    float ih = __fadd_rn(__fsub_rn(fminf(ay2, g[3]), fmaxf(ay1, g[1])), 1.0f);
    if (ih <= 0.0f) return 0.0f;
    float idp = __fadd_rn(__fsub_rn(fminf(az2, g[5]), fmaxf(az1, g[4])), 1.0f);
    if (idp <= 0.0f) return 0.0f;
    float inter = __fmul_rn(__fmul_rn(iw, ih), idp);
    float den   = __fsub_rn(__fadd_rn(aarea, g[6]), inter);
    return __fdiv_rn(inter, den);
}

__device__ __forceinline__ float f_area(float x1, float y1, float x2, float y2,
                                        float z1, float z2) {
    float aw = __fadd_rn(__fsub_rn(x2, x1), 1.0f);
    float ah = __fadd_rn(__fsub_rn(y2, y1), 1.0f);
    float ad = __fadd_rn(__fsub_rn(z2, z1), 1.0f);
    return __fmul_rn(__fmul_rn(aw, ah), ad);
}

// grid barrier: arrive (returns true for the LAST block), release, wait.
__device__ __forceinline__ bool bar_arrive(int p, int* sflag) {
    __syncthreads();
    if (threadIdx.x == 0) {
        __threadfence();                         // flush + (gpu-scope) order prior block stores
        int o = atomicAdd(&g_ctr[p], 1);
        *sflag = (o == G2 - 1) ? 1 : 0;
    }
    __syncthreads();
    return *sflag != 0;
}
__device__ __forceinline__ void bar_release(int p) {
    __syncthreads();
    if (threadIdx.x == 0) { __threadfence(); atomicExch(&g_rel[p], 1); }
}
__device__ __forceinline__ void bar_wait(int p) {
    if (threadIdx.x == 0) {
        while (atomicAdd(&g_rel[p], 0) == 0) __nanosleep(64);
        __threadfence();                         // invalidate L1 before cross-block reads
    }
    __syncthreads();
}

__global__ void __launch_bounds__(256, 2)
k_main(const float* __restrict__ gt, const float* __restrict__ im_info,
       const float* __restrict__ anchors, const float* __restrict__ rfg,
       const float* __restrict__ rbg, float* __restrict__ out) {
    __shared__ float sgt[NK * 7];
    __shared__ float sgm[NK];
    __shared__ float sanch[NA * 6];
    __shared__ float red[8][NK];
    __shared__ int   s40[NB * NK];
    __shared__ float sder[NA * 9];
    __shared__ float sgtd[NB * NK * 6];
    __shared__ unsigned long long sth[4];
    __shared__ int   scnt[2];
    __shared__ int   sflag;
    __shared__ unsigned long long sbuf8[CAP];     // 32KB: reused as hist chunk / key buffer

    const int tid = threadIdx.x;
    const int blk = blockIdx.x;
    const int b    = (blk >= HG) ? 1 : 0;
    const int lblk = blk - b * HG;
    const int lane = tid & 31, wid = tid >> 5;

    // ---- local tables ----
    if (tid < NA * 6) sanch[tid] = anchors[tid];
    if (tid < NK) {
        const float* g = gt + (b * NK + tid) * 7;
        float x1 = g[0], y1 = g[1], x2 = g[2], y2 = g[3], z1 = g[4], z2 = g[5];
        float gw = __fadd_rn(__fsub_rn(x2, x1), 1.0f);
        float gh = __fadd_rn(__fsub_rn(y2, y1), 1.0f);
        float gd = __fadd_rn(__fsub_rn(z2, z1), 1.0f);
        if (gw == 1.0f && gh == 1.0f && gd == 1.0f) { x2 = -1e9f; }   // zero-size gt => ov 0
        float* o = sgt + tid * 7;
        o[0] = x1; o[1] = y1; o[2] = x2; o[3] = y2; o[4] = z1; o[5] = z2;
        o[6] = __fmul_rn(__fmul_rn(gw, gh), gd);
    }
    __syncthreads();
    const float iH = im_info[0], iW = im_info[1], iD = im_info[2];

    // ---- hist zero (grid-stride, completes before bar0 < phase B atomics) ----
    {
        int z = blk * 256 + tid;
        if (z < 65536) ((uint4*)g_hist)[z] = make_uint4(0u, 0u, 0u, 0u);
    }

    // ================= phase A: per-block gt maxima =================
    {
        float vmax[NK];
#pragma unroll
        for (int k = 0; k < NK; k++) vmax[k] = -1.0f;
        for (int it = 0; it < NIT; it++) {
            int i = it * STR + lblk * 256 + tid;
            if (i >= TOTAL) break;                        // block-uniform (TOTAL % 256 == 0)
            int a = i % NA; int q = i / NA;
            int d = q % ND; q /= ND;
            int w = q % NW; int h = q / NW;
            float shx = w * 16.0f, shy = h * 16.0f, shz = d * 16.0f;
            const float* an = sanch + a * 6;
            float ax1 = an[0] + shx, ay1 = an[1] + shy;
            float ax2 = an[2] + shx, ay2 = an[3] + shy;
            float az1 = an[4] + shz, az2 = an[5] + shz;
            bool inside = (ax1 >= 0.0f) && (ay1 >= 0.0f) && (az1 >= 0.0f) &&
                          (ax2 < iW) && (ay2 < iH) && (az2 < iD);
            if (!inside) continue;
            float aarea = f_area(ax1, ay1, ax2, ay2, az1, az2);
#pragma unroll
            for (int k = 0; k < NK; k++) {
                float ov = f_ov(ax1, ay1, ax2, ay2, az1, az2, aarea, sgt + k * 7);
                vmax[k] = fmaxf(vmax[k], ov);
            }
        }
#pragma unroll
        for (int k = 0; k < NK; k++) {
            float v = vmax[k];
#pragma unroll
            for (int off = 16; off; off >>= 1) v = fmaxf(v, __shfl_xor_sync(0xFFFFFFFFu, v, off));
            if (lane == 0) red[wid][k] = v;
        }
        __syncthreads();
        if (tid < NK) {
            float m = red[0][tid];
#pragma unroll
            for (int wq = 1; wq < 8; wq++) m = fmaxf(m, red[wq][tid]);
            g_bmax[blk * NK + tid] = m;
        }
    }

    // ---- bar0: leader reduces g_bmax -> g_gm, computes g_gtd / g_ancd ----
    if (bar_arrive(0, &sflag)) {
        if (tid < NB * NK) s40[tid] = __float_as_int(-1.0f);
        __syncthreads();
        for (int j = tid; j < G2 * NK; j += 256) {
            int blkj = j / NK, kk = j % NK;
            int bb = (blkj >= HG) ? 1 : 0;
            atomicMax(&s40[bb * NK + kk], __float_as_int(g_bmax[j]));
        }
        __syncthreads();
        if (tid < NB * NK) {
            float gm = __int_as_float(s40[tid]);
            g_gm[tid] = (gm == 0.0f) ? 1e-5f : gm;
            const float* g = gt + tid * 7;
            float gw = g[2] - g[0] + 1.0f, gh = g[3] - g[1] + 1.0f, gd = g[5] - g[4] + 1.0f;
            float* o = g_gtd + tid * 6;
            o[0] = g[0] + 0.5f * (gw - 1.0f);
            o[1] = g[1] + 0.5f * (gh - 1.0f);
            o[2] = g[4] + 0.5f * (gd - 1.0f);
            o[3] = logf(gw); o[4] = logf(gh); o[5] = logf(gd);
        }
        if (tid >= 64 && tid < 64 + NA) {
            int a = tid - 64;
            const float* an = anchors + a * 6;
            float ew = an[2] - an[0] + 1.0f;
            float eh = an[3] - an[1] + 1.0f;
            float ed = an[5] - an[4] + 1.0f;
            float* o = g_ancd + a * 9;
            o[0] = an[0] + 0.5f * (ew - 1.0f);
            o[1] = an[1] + 0.5f * (eh - 1.0f);
            o[2] = an[4] + 0.5f * (ed - 1.0f);
            o[3] = 1.0f / ew; o[4] = 1.0f / eh; o[5] = 1.0f / ed;
            o[6] = logf(ew); o[7] = logf(eh); o[8] = logf(ed);
        }
        // first-run safety: g_act starts 0 from zero-init; must be 1
        if (tid == 200 && g_first) { g_act[0] = g_act[1] = g_act[2] = g_act[3] = 1; g_first = 0; }
        bar_release(0);
    } else bar_wait(0);

    if (tid < NK) sgm[tid] = g_gm[b * NK + tid];
    if (tid < 2) scnt[tid] = 0;
    __syncthreads();

    // ================= phase B: labels, argmax, hist, counts =================
    for (int it = 0; it < NIT; it++) {
        int i = it * STR + lblk * 256 + tid;
        if (i >= TOTAL) break;
        int e = b * TOTAL + i;
        int a = i % NA; int q = i / NA;
        int d = q % ND; q /= ND;
        int w = q % NW; int h = q / NW;
        float shx = w * 16.0f, shy = h * 16.0f, shz = d * 16.0f;
        const float* an = sanch + a * 6;
        float ax1 = an[0] + shx, ay1 = an[1] + shy;
        float ax2 = an[2] + shx, ay2 = an[3] + shy;
        float az1 = an[4] + shz, az2 = an[5] + shz;
        bool inside = (ax1 >= 0.0f) && (ay1 >= 0.0f) && (az1 >= 0.0f) &&
                      (ax2 < iW) && (ay2 < iH) && (az2 < iD);
        signed char lab = -1;
        unsigned char am = 0;
        if (inside) {
            float aarea = f_area(ax1, ay1, ax2, ay2, az1, az2);
            float best = -1.0f;
            int bi = 0;
            bool tie = false;
#pragma unroll
            for (int k = 0; k < NK; k++) {
                float ov = f_ov(ax1, ay1, ax2, ay2, az1, az2, aarea, sgt + k * 7);
                if (ov > best) { best = ov; bi = k; }
                if (ov == sgm[k]) tie = true;
            }
            lab = (tie || best >= 0.7f) ? 1 : ((best < 0.3f) ? 0 : -1);
            am = (unsigned char)bi;
        }
        g_label[e] = lab;
        g_amax[e]  = am;
        unsigned b1 = __ballot_sync(0xFFFFFFFFu, lab == 1);
        unsigned b0 = __ballot_sync(0xFFFFFFFFu, lab == 0);
        if (lane == 0) {
            if (b1) atomicAdd(&scnt[0], __popc(b1));
            if (b0) atomicAdd(&scnt[1], __popc(b0));
        }
        if (lab == 1) {
            unsigned bin = __float_as_uint(rfg[e]) >> 16;
            atomicAdd(&g_hist[(b * 2) * NBINS + bin], 1u);
        } else if (lab == 0) {
            unsigned bin = __float_as_uint(rbg[e]) >> 16;
            atomicAdd(&g_hist[(b * 2 + 1) * NBINS + bin], 1u);
        }
    }
    __syncthreads();
    if (tid < 2 && scnt[tid]) atomicAdd(&g_cnt[b * 2 + tid], scnt[tid]);

    // ---- bar1: hist complete ----
    if (bar_arrive(1, &sflag)) bar_release(1); else bar_wait(1);

    // ================= phase C: chunk sums (blocks 0..63) =================
    if (blk < 64) {
        int grp = blk >> 4, chunk = blk & 15;
        const uint4* hp = (const uint4*)(g_hist + grp * NBINS + chunk * 4096);
        unsigned s = 0;
#pragma unroll
        for (int j = 0; j < 4; j++) {
            uint4 v = hp[j * 256 + tid];
            s += v.x + v.y + v.z + v.w;
        }
#pragma unroll
        for (int off = 16; off; off >>= 1) s += __shfl_xor_sync(0xFFFFFFFFu, s, off);
        if (lane == 0) red[0][wid] = (float)0;   // (unused slot reuse guard)
        __shared__ unsigned wsum[8];
        if (lane == 0) wsum[wid] = s;
        __syncthreads();
        if (tid == 0) {
            unsigned tot = 0;
#pragma unroll
            for (int i2 = 0; i2 < 8; i2++) tot += wsum[i2];
            g_csum[grp * 16 + chunk] = tot;
        }
    }

    // ---- bar2: leader resolves threshold bins + wval ----
    if (bar_arrive(2, &sflag)) {
        unsigned* sb = (unsigned*)sbuf8;
        for (int g2 = 0; g2 < 4; g2++) {
            int m0;
            if ((g2 & 1) == 0) m0 = NUMFG;
            else { int fgc = g_cnt[g2 - 1]; int kept = (fgc < NUMFG) ? fgc : NUMFG; m0 = RPNB - kept; }
            if (g2 == 3 && tid == 0) {
                int fg1 = g_cnt[2]; if (fg1 > NUMFG) fg1 = NUMFG;
                int cap = RPNB - fg1;
                int bg1 = g_cnt[3]; if (bg1 > cap) bg1 = cap;
                int ne = fg1 + bg1;
                g_wval = 1.0f / (float)(ne > 0 ? ne : 1);
            }
            unsigned cs[16];
            unsigned total = 0;
#pragma unroll
            for (int c = 0; c < 16; c++) { cs[c] = g_csum[g2 * 16 + c]; total += cs[c]; }
            if ((unsigned)m0 >= total) {
                if (tid == 0) g_act[g2] = 0;
                continue;
            }
            int cstar = 0; unsigned acc = 0;
            for (int c = 15; c >= 0; c--) {
                if (acc + cs[c] >= (unsigned)m0) { cstar = c; break; }
                acc += cs[c];
            }
            int m_rem = m0 - (int)acc;
            const unsigned* hb = g_hist + g2 * NBINS + cstar * 4096;
            for (int i2 = tid; i2 < 4096; i2 += 256) sb[i2] = hb[i2];
            __syncthreads();
            if (tid < 32) {
                unsigned accw = 0;
                for (int basei = 4095; basei >= 31; basei -= 32) {
                    unsigned v = sb[basei - lane];
                    unsigned inc = v;
#pragma unroll
                    for (int off = 1; off < 32; off <<= 1) {
                        unsigned u = __shfl_up_sync(0xFFFFFFFFu, inc, off);
                        if (lane >= off) inc += u;
                    }
                    unsigned tot32 = __shfl_sync(0xFFFFFFFFu, inc, 31);
                    if (accw + tot32 >= (unsigned)m_rem) {
                        unsigned incl = accw + inc;
                        unsigned excl = incl - v;
                        if (excl < (unsigned)m_rem && (unsigned)m_rem <= incl) {
                            g_bin[g2] = (unsigned)(cstar * 4096 + basei - lane);
                            g_m[g2]   = m_rem - (int)excl;
                        }
                        break;
                    }
                    accw += tot32;
                }
            }
            __syncthreads();
        }
        bar_release(2);
    } else bar_wait(2);

    // ================= phase D: collect threshold-bin keys =================
    {
        int act0 = g_act[0], act1 = g_act[1], act2 = g_act[2], act3 = g_act[3];
        unsigned bin0 = g_bin[0], bin1 = g_bin[1], bin2 = g_bin[2], bin3 = g_bin[3];
        int acts[4] = {act0, act1, act2, act3};
        unsigned bins[4] = {bin0, bin1, bin2, bin3};
        for (int it = 0; it < NITC; it++) {
            int e = it * STRF + blk * 256 + tid;
            if (e >= NB * TOTAL) break;
            int lab = g_label[e];
            if (lab < 0) continue;
            int bb = (e >= TOTAL) ? 1 : 0;
            unsigned i = (unsigned)(e - bb * TOTAL);
            int grp = bb * 2 + (lab == 0 ? 1 : 0);
            if (!acts[grp]) continue;
            float rv = (lab == 1) ? rfg[e] : rbg[e];
            unsigned rb = __float_as_uint(rv);
            if ((rb >> 16) != bins[grp]) continue;
            unsigned long long key = ((unsigned long long)rb << 32) | (unsigned)(~i);
            int pos = atomicAdd(&g_ncand[grp], 1);
            if (pos < CAP) g_cand[grp * CAP + pos] = key;
        }
    }

    // ---- bar3: leader computes exact m-th largest per group ----
    if (bar_arrive(3, &sflag)) {
        for (int grp = 0; grp < 4; grp++) {
            if (!g_act[grp]) { if (tid == 0) g_thresh[grp] = 0ULL; continue; }
            int n = g_ncand[grp]; if (n > CAP) n = CAP;
            int m = g_m[grp];
            for (int i2 = tid; i2 < n; i2 += 256) sbuf8[i2] = g_cand[grp * CAP + i2];
            __syncthreads();
            for (int i2 = tid; i2 < n; i2 += 256) {
                unsigned long long k = sbuf8[i2];
                int cg = 0;
                for (int j = 0; j < n; j++) cg += (sbuf8[j] > k) ? 1 : 0;
                if (cg == m - 1) g_thresh[grp] = k;
            }
            __syncthreads();
        }
        bar_release(3);
    } else bar_wait(3);

    // ================= phase E: final labels + all outputs =================
    if (tid < NA * 9) sder[tid] = g_ancd[tid];
    if (tid < NB * NK * 6) sgtd[tid] = g_gtd[tid];
    if (tid < 4) sth[tid] = g_thresh[tid];
    __syncthreads();
    {
        float wv = g_wval;
        for (int it = 0; it < NITE; it++) {
            int item = it * STRF + blk * 256 + tid;
            if (item >= OUTTOT / 4) break;
            int idx = item * 4;
            int d0 = idx % ND; int q = idx / ND;
            int w = q % NW; q /= NW;
            int h = q % NH; q /= NH;
            int a = q % NA; int bb = q / NA;
            int pix0 = (h * NW + w) * ND + d0;

            const float* an = sanch + a * 6;       // anchors identical across batches
            const float* ad = sder + a * 9;
            float shx = w * 16.0f, shy = h * 16.0f;
            float ax1 = an[0] + shx, ay1 = an[1] + shy;
            float ax2 = an[2] + shx, ay2 = an[3] + shy;
            bool inxy = (ax1 >= 0.0f) && (ay1 >= 0.0f) && (ax2 < iW) && (ay2 < iH);

            float lb[4], ivv[4], ovv[4];
            float T[6][4];
#pragma unroll
            for (int j = 0; j < 4; j++) {
                float shz = (float)(d0 + j) * 16.0f;
                float az1 = an[4] + shz, az2 = an[5] + shz;
                bool inside = inxy && (az1 >= 0.0f) && (az2 < iD);
                int ia = (pix0 + j) * NA + a;
                int e  = bb * TOTAL + ia;
                int lab = (int)g_label[e];
                if (lab >= 0) {
                    int grp = bb * 2 + (lab == 0 ? 1 : 0);
                    float rv = (lab == 1) ? rfg[e] : rbg[e];
                    unsigned long long key =
                        ((unsigned long long)__float_as_uint(rv) << 32) | (unsigned)(~(unsigned)ia);
                    if (key < sth[grp]) lab = -1;
                }
                float t0 = 0.0f, t1 = 0.0f, t2 = 0.0f, t3 = 0.0f, t4 = 0.0f, t5 = 0.0f;
                if (inside) {
                    int am = (int)g_amax[e];
                    const float* gd = sgtd + (bb * NK + am) * 6;
                    t0 = (gd[0] - ad[0] - shx) * ad[3];
                    t1 = (gd[1] - ad[1] - shy) * ad[4];
                    t2 = (gd[2] - ad[2] - shz) * ad[5];
                    t3 = gd[3] - ad[6];
                    t4 = gd[4] - ad[7];
                    t5 = gd[5] - ad[8];
                }
                T[0][j] = t0; T[1][j] = t1; T[2][j] = t2;
                T[3][j] = t3; T[4][j] = t4; T[5][j] = t5;
                lb[j]  = (float)lab;
                ivv[j] = (lab == 1) ? 1.0f : 0.0f;
                ovv[j] = (lab >= 0) ? wv : 0.0f;
            }

            *(float4*)(out + idx) = make_float4(lb[0], lb[1], lb[2], lb[3]);
            long long base = (long long)(bb * 54 + a * 6) * HWD + pix0;
            float* bt = out + OFF_BT + base;
#pragma unroll
            for (int c = 0; c < 6; c++)
                *(float4*)(bt + c * HWD) = make_float4(T[c][0], T[c][1], T[c][2], T[c][3]);
            float* iwp = out + OFF_IW + base;
            float* owp = out + OFF_OW + base;
            float4 iv = make_float4(ivv[0], ivv[1], ivv[2], ivv[3]);
            float4 ov = make_float4(ovv[0], ovv[1], ovv[2], ovv[3]);
#pragma unroll
            for (int c = 0; c < 6; c++) {
                *(float4*)(iwp + c * HWD) = iv;
                *(float4*)(owp + c * HWD) = ov;
            }
        }
    }

    // ---- bar4: last block resets all state for the next run ----
    __syncthreads();
    if (threadIdx.x == 0) {
        __threadfence();
        int o = atomicAdd(&g_ctr[4], 1);
        sflag = (o == G2 - 1) ? 1 : 0;
    }
    __syncthreads();
    if (sflag) {
        if (tid < 5) { g_ctr[tid] = 0; g_rel[tid] = 0; }
        if (tid >= 8 && tid < 12) {
            int g2 = tid - 8;
            g_cnt[g2] = 0; g_ncand[g2] = 0; g_act[g2] = 1;
            g_thresh[g2] = 0ULL; g_m[g2] = 0; g_bin[g2] = 0u;
        }
    }
}

// ---------------- launch ----------------
extern "C" void kernel_launch(void* const* d_in, const int* in_sizes, int n_in,
                              void* d_out, int out_size) {
    const float* gt      = (const float*)d_in[1];
    const float* im_info = (const float*)d_in[2];
    const float* anchors = (const float*)d_in[4];
    const float* rfg     = (const float*)d_in[5];
    const float* rbg     = (const float*)d_in[6];
    float* out           = (float*)d_out;

    k_main<<<G2, 256>>>(gt, im_info, anchors, rfg, rbg, out);
}

// round 8
// speedup vs baseline: 1.0568x; 1.0568x over previous
#include <cuda_runtime.h>
#include <cuda_bf16.h>
#include <stdint.h>

#define NB 2
#define NH 48
#define NW 48
#define ND 24
#define NA 9
#define NK 20
#define TOTAL  497664            // NH*NW*ND*NA
#define HWD    55296             // NH*NW*ND
#define OUTTOT 995328            // NB*NA*HWD
#define NUMFG 128
#define RPNB  256
#define NBINS 65536
#define CAP   4096
#define BPB   243                // blocks per batch in pass1/2 (2048 anchors each)

#define G3   296                 // persistent grid (2/SM on 148 SMs)
#define STRF (G3 * 256)          // 75776

#define OFF_BT  995328
#define OFF_IW  (OFF_BT + 5971968)
#define OFF_OW  (OFF_IW + 5971968)

// ---------------- device scratch (zero-init; reset by k_sel's final barrier) ------
__device__ int                g_ctr[3];
__device__ int                g_rel[2];
__device__ int                g_gtmax[NB * NK];     // float bits; 0 == -1 here (ov>=0)
__device__ float              g_best[NB * TOTAL];   // per-anchor best ov (-1 outside)
__device__ unsigned char      g_amax[NB * TOTAL];
__device__ signed char        g_label[NB * TOTAL];
__device__ int                g_cnt[4];
__device__ unsigned int       g_hist[4 * NBINS];
__device__ unsigned int       g_csum[64];
__device__ unsigned int       g_bin[4];
__device__ int                g_m[4];
__device__ int                g_keep[4];            // 1 => keep all (inverted; 0-init = active)
__device__ int                g_ncand[4];
__device__ unsigned long long g_cand[4 * CAP];
__device__ unsigned long long g_thresh[4];
__device__ float              g_wval;

// IoU with strict _rn intrinsics: bitwise identical in pass1 and pass2.
__device__ __forceinline__ float f_ov(float ax1, float ay1, float ax2, float ay2,
                                      float az1, float az2, float aarea,
                                      const float* __restrict__ g) {
    float iw = __fadd_rn(__fsub_rn(fminf(ax2, g[2]), fmaxf(ax1, g[0])), 1.0f);
    if (iw <= 0.0f) return 0.0f;
    float ih = __fadd_rn(__fsub_rn(fminf(ay2, g[3]), fmaxf(ay1, g[1])), 1.0f);
    if (ih <= 0.0f) return 0.0f;
    float idp = __fadd_rn(__fsub_rn(fminf(az2, g[5]), fmaxf(az1, g[4])), 1.0f);
    if (idp <= 0.0f) return 0.0f;
    float inter = __fmul_rn(__fmul_rn(iw, ih), idp);
    float den   = __fsub_rn(__fadd_rn(aarea, g[6]), inter);
    return __fdiv_rn(inter, den);
}

__device__ __forceinline__ float f_area(float x1, float y1, float x2, float y2,
                                        float z1, float z2) {
    float aw = __fadd_rn(__fsub_rn(x2, x1), 1.0f);
    float ah = __fadd_rn(__fsub_rn(y2, y1), 1.0f);
    float ad = __fadd_rn(__fsub_rn(z2, z1), 1.0f);
    return __fmul_rn(__fmul_rn(aw, ah), ad);
}

// build per-batch gt table in smem (identical math in both passes)
__device__ __forceinline__ void build_sgt(float* sgt, const float* __restrict__ gt, int b) {
    int tid = threadIdx.x;
    if (tid < NK) {
        const float* g = gt + (b * NK + tid) * 7;
        float x1 = g[0], y1 = g[1], x2 = g[2], y2 = g[3], z1 = g[4], z2 = g[5];
        float gw = __fadd_rn(__fsub_rn(x2, x1), 1.0f);
        float gh = __fadd_rn(__fsub_rn(y2, y1), 1.0f);
        float gd = __fadd_rn(__fsub_rn(z2, z1), 1.0f);
        if (gw == 1.0f && gh == 1.0f && gd == 1.0f) { x2 = -1e9f; }   // zero-size => ov 0
        float* o = sgt + tid * 7;
        o[0] = x1; o[1] = y1; o[2] = x2; o[3] = y2; o[4] = z1; o[5] = z2;
        o[6] = __fmul_rn(__fmul_rn(gw, gh), gd);
    }
}

// ================= pass1: hist zero + per-anchor best/argmax + per-gt max ========
__global__ void __launch_bounds__(256) k_pass1(const float* __restrict__ gt,
                                               const float* __restrict__ im_info,
                                               const float* __restrict__ anchors) {
    {   // zero histogram (65536 uint4 across 124416 threads)
        int z = blockIdx.x * 256 + threadIdx.x;
        if (z < 65536) ((uint4*)g_hist)[z] = make_uint4(0u, 0u, 0u, 0u);
    }
    int b    = blockIdx.x / BPB;
    int base = (blockIdx.x % BPB) * 2048;
    __shared__ float sgt[NK * 7];
    __shared__ float sanch[NA * 6];
    __shared__ float red[8][NK];
    build_sgt(sgt, gt, b);
    if (threadIdx.x < NA * 6) sanch[threadIdx.x] = anchors[threadIdx.x];
    __syncthreads();
    float iH = im_info[0], iW = im_info[1], iD = im_info[2];

    float vmax[NK];
#pragma unroll
    for (int k = 0; k < NK; k++) vmax[k] = -1.0f;

    for (int t = 0; t < 8; t++) {
        int i = base + t * 256 + threadIdx.x;
        int e = b * TOTAL + i;
        int a = i % NA; int q = i / NA;
        int d = q % ND; q /= ND;
        int w = q % NW; int h = q / NW;
        float shx = w * 16.0f, shy = h * 16.0f, shz = d * 16.0f;
        const float* an = sanch + a * 6;
        float ax1 = an[0] + shx, ay1 = an[1] + shy;
        float ax2 = an[2] + shx, ay2 = an[3] + shy;
        float az1 = an[4] + shz, az2 = an[5] + shz;
        bool inside = (ax1 >= 0.0f) && (ay1 >= 0.0f) && (az1 >= 0.0f) &&
                      (ax2 < iW) && (ay2 < iH) && (az2 < iD);
        float best = -1.0f;
        int bi = 0;
        if (inside) {
            best = 0.0f;   // inside anchors: ov >= 0; reference best from ovs (all >= 0)
            best = -1.0f;
            float aarea = f_area(ax1, ay1, ax2, ay2, az1, az2);
#pragma unroll
            for (int k = 0; k < NK; k++) {
                float ov = f_ov(ax1, ay1, ax2, ay2, az1, az2, aarea, sgt + k * 7);
                if (ov > best) { best = ov; bi = k; }
                vmax[k] = fmaxf(vmax[k], ov);
            }
        }
        g_best[e] = best;                 // -1 only possible sentinel for outside...
        if (!inside) g_best[e] = -1.0f;   // (inside best >= 0 since ov >= 0)
        g_amax[e] = (unsigned char)bi;
    }
    int lane = threadIdx.x & 31, wid = threadIdx.x >> 5;
#pragma unroll
    for (int k = 0; k < NK; k++) {
        float v = vmax[k];
#pragma unroll
        for (int off = 16; off; off >>= 1) v = fmaxf(v, __shfl_xor_sync(0xFFFFFFFFu, v, off));
        if (lane == 0) red[wid][k] = v;
    }
    __syncthreads();
    if (threadIdx.x < NK) {
        float m = red[0][threadIdx.x];
#pragma unroll
        for (int wq = 1; wq < 8; wq++) m = fmaxf(m, red[wq][threadIdx.x]);
        if (m > 0.0f) atomicMax(&g_gtmax[b * NK + threadIdx.x], __float_as_int(m));
    }
}

// ================= pass2: labels via stored best; sparse tie recompute ===========
__global__ void __launch_bounds__(256) k_pass2(const float* __restrict__ gt,
                                               const float* __restrict__ im_info,
                                               const float* __restrict__ anchors,
                                               const float* __restrict__ rfg,
                                               const float* __restrict__ rbg) {
    int b    = blockIdx.x / BPB;
    int base = (blockIdx.x % BPB) * 2048;
    __shared__ float sgt[NK * 7];
    __shared__ float sgm[NK];
    __shared__ float sanch[NA * 6];
    __shared__ float sminT;
    __shared__ int   scnt[2];
    build_sgt(sgt, gt, b);
    if (threadIdx.x < NK) {
        float gm = __int_as_float(g_gtmax[b * NK + threadIdx.x]);
        sgm[threadIdx.x] = (gm == 0.0f) ? 1e-5f : gm;
    }
    if (threadIdx.x < NA * 6) sanch[threadIdx.x] = anchors[threadIdx.x];
    if (threadIdx.x < 2) scnt[threadIdx.x] = 0;
    __syncthreads();
    if (threadIdx.x == 0) {
        float mn = sgm[0];
#pragma unroll
        for (int k = 1; k < NK; k++) mn = fminf(mn, sgm[k]);
        sminT = mn;
    }
    __syncthreads();
    float minT = sminT;
    int lane = threadIdx.x & 31;

    for (int t = 0; t < 8; t++) {
        int i = base + t * 256 + threadIdx.x;
        int e = b * TOTAL + i;
        float best = g_best[e];
        signed char lab = -1;
        if (best >= 0.0f) {
            bool tie = false;
            if (best >= minT) {
                // sparse exact tie recompute (bitwise identical f_ov)
                int a = i % NA; int q = i / NA;
                int d = q % ND; q /= ND;
                int w = q % NW; int h = q / NW;
                float shx = w * 16.0f, shy = h * 16.0f, shz = d * 16.0f;
                const float* an = sanch + a * 6;
                float ax1 = an[0] + shx, ay1 = an[1] + shy;
                float ax2 = an[2] + shx, ay2 = an[3] + shy;
                float az1 = an[4] + shz, az2 = an[5] + shz;
                float aarea = f_area(ax1, ay1, ax2, ay2, az1, az2);
#pragma unroll
                for (int k = 0; k < NK; k++) {
                    float ov = f_ov(ax1, ay1, ax2, ay2, az1, az2, aarea, sgt + k * 7);
                    if (ov == sgm[k]) tie = true;
                }
            }
            lab = (tie || best >= 0.7f) ? 1 : ((best < 0.3f) ? 0 : -1);
        }
        g_label[e] = lab;

        unsigned b1 = __ballot_sync(0xFFFFFFFFu, lab == 1);
        unsigned b0 = __ballot_sync(0xFFFFFFFFu, lab == 0);
        if (lane == 0) {
            if (b1) atomicAdd(&scnt[0], __popc(b1));
            if (b0) atomicAdd(&scnt[1], __popc(b0));
        }
        if (lab == 1) {
            unsigned bin = __float_as_uint(rfg[e]) >> 16;
            atomicAdd(&g_hist[(b * 2) * NBINS + bin], 1u);
        } else if (lab == 0) {
            unsigned bin = __float_as_uint(rbg[e]) >> 16;
            atomicAdd(&g_hist[(b * 2 + 1) * NBINS + bin], 1u);
        }
    }
    __syncthreads();
    if (threadIdx.x < 2 && scnt[threadIdx.x]) atomicAdd(&g_cnt[b * 2 + threadIdx.x], scnt[threadIdx.x]);
}

// ================= k_sel: persistent selection + output ==========================
__global__ void __launch_bounds__(256, 2)
k_sel(const float* __restrict__ gt, const float* __restrict__ im_info,
      const float* __restrict__ anchors, const float* __restrict__ rfg,
      const float* __restrict__ rbg, float* __restrict__ out) {
    __shared__ unsigned long long sbuf8[CAP];     // 32KB, reused
    __shared__ float sanch[NA * 6];
    __shared__ float sder[NA * 9];
    __shared__ float sgtd[NB * NK * 6];
    __shared__ unsigned long long sth[4];
    __shared__ int   sflag;
    const int tid = threadIdx.x, blk = blockIdx.x;
    const int lane = tid & 31, wid = tid >> 5;

    // ---- phase C: histogram chunk sums (blocks 0..63) ----
    if (blk < 64) {
        int grp = blk >> 4, chunk = blk & 15;
        const uint4* hp = (const uint4*)(g_hist + grp * NBINS + chunk * 4096);
        unsigned s = 0;
#pragma unroll
        for (int j = 0; j < 4; j++) {
            uint4 v = hp[j * 256 + tid];
            s += v.x + v.y + v.z + v.w;
        }
#pragma unroll
        for (int off = 16; off; off >>= 1) s += __shfl_xor_sync(0xFFFFFFFFu, s, off);
        __shared__ unsigned wsum[8];
        if (lane == 0) wsum[wid] = s;
        __syncthreads();
        if (tid == 0) {
            unsigned tot = 0;
#pragma unroll
            for (int i2 = 0; i2 < 8; i2++) tot += wsum[i2];
            g_csum[grp * 16 + chunk] = tot;
        }
    }

    // ---- bar0 (+ resolve by last arriver) ----
    __syncthreads();
    if (tid == 0) {
        __threadfence();
        int o = atomicAdd(&g_ctr[0], 1);
        sflag = (o == G3 - 1) ? 1 : 0;
    }
    __syncthreads();
    if (sflag) {
        unsigned* sb = (unsigned*)sbuf8;
        for (int g2 = 0; g2 < 4; g2++) {
            int m0;
            if ((g2 & 1) == 0) m0 = NUMFG;
            else { int fgc = g_cnt[g2 - 1]; int kept = (fgc < NUMFG) ? fgc : NUMFG; m0 = RPNB - kept; }
            if (g2 == 3 && tid == 0) {
                int fg1 = g_cnt[2]; if (fg1 > NUMFG) fg1 = NUMFG;
                int cap = RPNB - fg1;
                int bg1 = g_cnt[3]; if (bg1 > cap) bg1 = cap;
                int ne = fg1 + bg1;
                g_wval = 1.0f / (float)(ne > 0 ? ne : 1);
            }
            unsigned cs[16];
            unsigned total = 0;
#pragma unroll
            for (int c = 0; c < 16; c++) { cs[c] = g_csum[g2 * 16 + c]; total += cs[c]; }
            if ((unsigned)m0 >= total) {
                if (tid == 0) { g_keep[g2] = 1; g_thresh[g2] = 0ULL; }
                continue;
            }
            int cstar = 0; unsigned acc = 0;
            for (int c = 15; c >= 0; c--) {
                if (acc + cs[c] >= (unsigned)m0) { cstar = c; break; }
                acc += cs[c];
            }
            int m_rem = m0 - (int)acc;
            const unsigned* hb = g_hist + g2 * NBINS + cstar * 4096;
            for (int i2 = tid; i2 < 4096; i2 += 256) sb[i2] = hb[i2];
            __syncthreads();
            if (tid < 32) {
                unsigned accw = 0;
                for (int basei = 4095; basei >= 31; basei -= 32) {
                    unsigned v = sb[basei - lane];
                    unsigned inc = v;
#pragma unroll
                    for (int off = 1; off < 32; off <<= 1) {
                        unsigned u = __shfl_up_sync(0xFFFFFFFFu, inc, off);
                        if (lane >= off) inc += u;
                    }
                    unsigned tot32 = __shfl_sync(0xFFFFFFFFu, inc, 31);
                    if (accw + tot32 >= (unsigned)m_rem) {
                        unsigned incl = accw + inc;
                        unsigned excl = incl - v;
                        if (excl < (unsigned)m_rem && (unsigned)m_rem <= incl) {
                            g_bin[g2] = (unsigned)(cstar * 4096 + basei - lane);
                            g_m[g2]   = m_rem - (int)excl;
                        }
                        break;
                    }
                    accw += tot32;
                }
            }
            __syncthreads();
        }
        __syncthreads();
        if (tid == 0) { __threadfence(); atomicExch(&g_rel[0], 1); }
    } else {
        if (tid == 0) {
            while (atomicAdd(&g_rel[0], 0) == 0) __nanosleep(64);
            __threadfence();
        }
        __syncthreads();
    }

    // ---- phase D: collect threshold-bin keys ----
    {
        int keeps[4]; unsigned bins[4];
#pragma unroll
        for (int g2 = 0; g2 < 4; g2++) { keeps[g2] = g_keep[g2]; bins[g2] = g_bin[g2]; }
        for (int it = 0; it < 14; it++) {
            int e = it * STRF + blk * 256 + tid;
            if (e >= NB * TOTAL) break;
            int lab = g_label[e];
            if (lab < 0) continue;
            int bb = (e >= TOTAL) ? 1 : 0;
            unsigned i = (unsigned)(e - bb * TOTAL);
            int grp = bb * 2 + (lab == 0 ? 1 : 0);
            if (keeps[grp]) continue;
            float rv = (lab == 1) ? rfg[e] : rbg[e];
            unsigned rb = __float_as_uint(rv);
            if ((rb >> 16) != bins[grp]) continue;
            unsigned long long key = ((unsigned long long)rb << 32) | (unsigned)(~i);
            int pos = atomicAdd(&g_ncand[grp], 1);
            if (pos < CAP) g_cand[grp * CAP + pos] = key;
        }
    }

    // ---- bar1 (+ exact m-th key by last arriver) ----
    __syncthreads();
    if (tid == 0) {
        __threadfence();
        int o = atomicAdd(&g_ctr[1], 1);
        sflag = (o == G3 - 1) ? 1 : 0;
    }
    __syncthreads();
    if (sflag) {
        for (int grp = 0; grp < 4; grp++) {
            if (g_keep[grp]) continue;
            int n = g_ncand[grp]; if (n > CAP) n = CAP;
            int m = g_m[grp];
            for (int i2 = tid; i2 < n; i2 += 256) sbuf8[i2] = g_cand[grp * CAP + i2];
            __syncthreads();
            for (int i2 = tid; i2 < n; i2 += 256) {
                unsigned long long k = sbuf8[i2];
                int cg = 0;
                for (int j = 0; j < n; j++) cg += (sbuf8[j] > k) ? 1 : 0;
                if (cg == m - 1) g_thresh[grp] = k;
            }
            __syncthreads();
        }
        __syncthreads();
        if (tid == 0) { __threadfence(); atomicExch(&g_rel[1], 1); }
    } else {
        if (tid == 0) {
            while (atomicAdd(&g_rel[1], 0) == 0) __nanosleep(64);
            __threadfence();
        }
        __syncthreads();
    }

    // ---- phase E: final labels + all outputs ----
    if (tid < NA * 6) sanch[tid] = anchors[tid];
    if (tid < 4) sth[tid] = g_thresh[tid];
    if (tid >= 32 && tid < 32 + NA) {                 // anchor derived table
        int a = tid - 32;
        const float* an = anchors + a * 6;
        float ew = an[2] - an[0] + 1.0f;
        float eh = an[3] - an[1] + 1.0f;
        float ed = an[5] - an[4] + 1.0f;
        float* o = sder + a * 9;
        o[0] = an[0] + 0.5f * (ew - 1.0f);
        o[1] = an[1] + 0.5f * (eh - 1.0f);
        o[2] = an[4] + 0.5f * (ed - 1.0f);
        o[3] = 1.0f / ew; o[4] = 1.0f / eh; o[5] = 1.0f / ed;
        o[6] = logf(ew); o[7] = logf(eh); o[8] = logf(ed);
    }
    if (tid >= 64 && tid < 64 + NB * NK) {            // gt derived table
        int j = tid - 64;
        const float* g = gt + j * 7;
        float gw = g[2] - g[0] + 1.0f, gh = g[3] - g[1] + 1.0f, gd = g[5] - g[4] + 1.0f;
        float* o = sgtd + j * 6;
        o[0] = g[0] + 0.5f * (gw - 1.0f);
        o[1] = g[1] + 0.5f * (gh - 1.0f);
        o[2] = g[4] + 0.5f * (gd - 1.0f);
        o[3] = logf(gw); o[4] = logf(gh); o[5] = logf(gd);
    }
    __syncthreads();
    {
        const float iH = im_info[0], iW = im_info[1], iD = im_info[2];
        float wv = g_wval;
        for (int it = 0; it < 4; it++) {
            int item = it * STRF + blk * 256 + tid;
            if (item >= OUTTOT / 4) break;
            int idx = item * 4;
            int d0 = idx % ND; int q = idx / ND;
            int w = q % NW; q /= NW;
            int h = q % NH; q /= NH;
            int a = q % NA; int bb = q / NA;
            int pix0 = (h * NW + w) * ND + d0;

            const float* an = sanch + a * 6;
            const float* ad = sder + a * 9;
            float shx = w * 16.0f, shy = h * 16.0f;
            float ax1 = an[0] + shx, ay1 = an[1] + shy;
            float ax2 = an[2] + shx, ay2 = an[3] + shy;
            bool inxy = (ax1 >= 0.0f) && (ay1 >= 0.0f) && (ax2 < iW) && (ay2 < iH);

            float lb[4], ivv[4], ovv[4];
            float T[6][4];
#pragma unroll
            for (int j = 0; j < 4; j++) {
                float shz = (float)(d0 + j) * 16.0f;
                float az1 = an[4] + shz, az2 = an[5] + shz;
                bool inside = inxy && (az1 >= 0.0f) && (az2 < iD);
                int ia = (pix0 + j) * NA + a;
                int e  = bb * TOTAL + ia;
                int lab = (int)g_label[e];
                if (lab >= 0) {
                    int grp = bb * 2 + (lab == 0 ? 1 : 0);
                    float rv = (lab == 1) ? rfg[e] : rbg[e];
                    unsigned long long key =
                        ((unsigned long long)__float_as_uint(rv) << 32) | (unsigned)(~(unsigned)ia);
                    if (key < sth[grp]) lab = -1;
                }
                float t0 = 0.0f, t1 = 0.0f, t2 = 0.0f, t3 = 0.0f, t4 = 0.0f, t5 = 0.0f;
                if (inside) {
                    int am = (int)g_amax[e];
                    const float* gd = sgtd + (bb * NK + am) * 6;
                    t0 = (gd[0] - ad[0] - shx) * ad[3];
                    t1 = (gd[1] - ad[1] - shy) * ad[4];
                    t2 = (gd[2] - ad[2] - shz) * ad[5];
                    t3 = gd[3] - ad[6];
                    t4 = gd[4] - ad[7];
                    t5 = gd[5] - ad[8];
                }
                T[0][j] = t0; T[1][j] = t1; T[2][j] = t2;
                T[3][j] = t3; T[4][j] = t4; T[5][j] = t5;
                lb[j]  = (float)lab;
                ivv[j] = (lab == 1) ? 1.0f : 0.0f;
                ovv[j] = (lab >= 0) ? wv : 0.0f;
            }

            *(float4*)(out + idx) = make_float4(lb[0], lb[1], lb[2], lb[3]);
            long long base = (long long)(bb * 54 + a * 6) * HWD + pix0;
            float* bt = out + OFF_BT + base;
#pragma unroll
            for (int c = 0; c < 6; c++)
                *(float4*)(bt + c * HWD) = make_float4(T[c][0], T[c][1], T[c][2], T[c][3]);
            float* iwp = out + OFF_IW + base;
            float* owp = out + OFF_OW + base;
            float4 iv = make_float4(ivv[0], ivv[1], ivv[2], ivv[3]);
            float4 ov = make_float4(ovv[0], ovv[1], ovv[2], ovv[3]);
#pragma unroll
            for (int c = 0; c < 6; c++) {
                *(float4*)(iwp + c * HWD) = iv;
                *(float4*)(owp + c * HWD) = ov;
            }
        }
    }

    // ---- final arrive-only barrier: last block resets state for next replay ----
    __syncthreads();
    if (tid == 0) {
        __threadfence();
        int o = atomicAdd(&g_ctr[2], 1);
        sflag = (o == G3 - 1) ? 1 : 0;
    }
    __syncthreads();
    if (sflag) {
        if (tid < 3)  g_ctr[tid] = 0;
        if (tid >= 4 && tid < 6)  g_rel[tid - 4] = 0;
        if (tid >= 8 && tid < 12) {
            int g2 = tid - 8;
            g_cnt[g2] = 0; g_ncand[g2] = 0; g_keep[g2] = 0;
        }
        if (tid >= 32 && tid < 32 + NB * NK) g_gtmax[tid - 32] = 0;
    }
}

// ---------------- launch ----------------
extern "C" void kernel_launch(void* const* d_in, const int* in_sizes, int n_in,
                              void* d_out, int out_size) {
    const float* gt      = (const float*)d_in[1];
    const float* im_info = (const float*)d_in[2];
    const float* anchors = (const float*)d_in[4];
    const float* rfg     = (const float*)d_in[5];
    const float* rbg     = (const float*)d_in[6];
    float* out           = (float*)d_out;

    k_pass1<<<NB * BPB, 256>>>(gt, im_info, anchors);
    k_pass2<<<NB * BPB, 256>>>(gt, im_info, anchors, rfg, rbg);
    k_sel<<<G3, 256>>>(gt, im_info, anchors, rfg, rbg, out);
}

// round 9
// speedup vs baseline: 1.5481x; 1.4649x over previous
#include <cuda_runtime.h>
#include <cuda_bf16.h>
#include <stdint.h>

#define NB 2
#define NH 48
#define NW 48
#define ND 24
#define NA 9
#define NK 20
#define TOTAL  497664            // NH*NW*ND*NA
#define HWD    55296             // NH*NW*ND
#define OUTTOT 995328            // NB*NA*HWD
#define NUMFG 128
#define RPNB  256
#define NBINS 65536
#define CAP   4096
#define BPB   243                // blocks per batch in passA/B (2048 anchors each)

#define OFF_BT  995328
#define OFF_IW  (OFF_BT + 5971968)
#define OFF_OW  (OFF_IW + 5971968)

// ------------- device scratch (zero-init at load; reset by passD block 0) -------
__device__ int                g_gtmax[NB * NK];     // float bits of max ov (>=0); 0-init ok
__device__ signed char        g_label[NB * TOTAL];
__device__ unsigned char      g_amax[NB * TOTAL];
__device__ int                g_cnt[4];
__device__ unsigned int       g_hist[4 * NBINS];
__device__ unsigned int       g_csum[64];
__device__ unsigned int       g_bin[4];
__device__ int                g_m[4];
__device__ int                g_keep[4];            // 1 => keep all (0-init = active)
__device__ int                g_ncand[4];
__device__ unsigned long long g_cand[4 * CAP];
__device__ unsigned long long g_thresh[4];
__device__ int                g_done_u;
__device__ float              g_wval;

// IoU with strict _rn intrinsics: bitwise identical in passA and passB.
__device__ __forceinline__ float f_ov(float ax1, float ay1, float ax2, float ay2,
                                      float az1, float az2, float aarea,
                                      const float* __restrict__ g) {
    float iw = __fadd_rn(__fsub_rn(fminf(ax2, g[2]), fmaxf(ax1, g[0])), 1.0f);
    if (iw <= 0.0f) return 0.0f;
    float ih = __fadd_rn(__fsub_rn(fminf(ay2, g[3]), fmaxf(ay1, g[1])), 1.0f);
    if (ih <= 0.0f) return 0.0f;
    float idp = __fadd_rn(__fsub_rn(fminf(az2, g[5]), fmaxf(az1, g[4])), 1.0f);
    if (idp <= 0.0f) return 0.0f;
    float inter = __fmul_rn(__fmul_rn(iw, ih), idp);
    float den   = __fsub_rn(__fadd_rn(aarea, g[6]), inter);
    return __fdiv_rn(inter, den);
}

__device__ __forceinline__ float f_area(float x1, float y1, float x2, float y2,
                                        float z1, float z2) {
    float aw = __fadd_rn(__fsub_rn(x2, x1), 1.0f);
    float ah = __fadd_rn(__fsub_rn(y2, y1), 1.0f);
    float ad = __fadd_rn(__fsub_rn(z2, z1), 1.0f);
    return __fmul_rn(__fmul_rn(aw, ah), ad);
}

__device__ __forceinline__ void build_sgt(float* sgt, const float* __restrict__ gt, int b) {
    int tid = threadIdx.x;
    if (tid < NK) {
        const float* g = gt + (b * NK + tid) * 7;
        float x1 = g[0], y1 = g[1], x2 = g[2], y2 = g[3], z1 = g[4], z2 = g[5];
        float gw = __fadd_rn(__fsub_rn(x2, x1), 1.0f);
        float gh = __fadd_rn(__fsub_rn(y2, y1), 1.0f);
        float gd = __fadd_rn(__fsub_rn(z2, z1), 1.0f);
        if (gw == 1.0f && gh == 1.0f && gd == 1.0f) { x2 = -1e9f; }   // zero-size => ov 0
        float* o = sgt + tid * 7;
        o[0] = x1; o[1] = y1; o[2] = x2; o[3] = y2; o[4] = z1; o[5] = z2;
        o[6] = __fmul_rn(__fmul_rn(gw, gh), gd);
    }
}

// ================= passA: hist zero + per-gt max (gt-tiled for low regs) =========
__global__ void __launch_bounds__(256, 4) k_passA(const float* __restrict__ gt,
                                                  const float* __restrict__ im_info,
                                                  const float* __restrict__ anchors) {
    {   // zero histogram (65536 uint4 across first 65536 threads)
        int z = blockIdx.x * 256 + threadIdx.x;
        if (z < 65536) ((uint4*)g_hist)[z] = make_uint4(0u, 0u, 0u, 0u);
    }
    int b    = blockIdx.x / BPB;
    int base = (blockIdx.x % BPB) * 2048;
    __shared__ float sgt[NK * 7];
    __shared__ float sanch[NA * 6];
    __shared__ int   smax[NK];
    build_sgt(sgt, gt, b);
    if (threadIdx.x < NA * 6) sanch[threadIdx.x] = anchors[threadIdx.x];
    if (threadIdx.x < NK) smax[threadIdx.x] = 0;
    __syncthreads();
    const float iH = im_info[0], iW = im_info[1], iD = im_info[2];
    const int lane = threadIdx.x & 31;

#pragma unroll 1
    for (int tile = 0; tile < 4; tile++) {
        float vmax[5];
#pragma unroll
        for (int k2 = 0; k2 < 5; k2++) vmax[k2] = 0.0f;
#pragma unroll 1
        for (int t = 0; t < 8; t++) {
            int i = base + t * 256 + threadIdx.x;
            int a = i % NA; int q = i / NA;
            int d = q % ND; q /= ND;
            int w = q % NW; int h = q / NW;
            float shx = w * 16.0f, shy = h * 16.0f, shz = d * 16.0f;
            const float* an = sanch + a * 6;
            float ax1 = an[0] + shx, ay1 = an[1] + shy;
            float ax2 = an[2] + shx, ay2 = an[3] + shy;
            float az1 = an[4] + shz, az2 = an[5] + shz;
            bool inside = (ax1 >= 0.0f) && (ay1 >= 0.0f) && (az1 >= 0.0f) &&
                          (ax2 < iW) && (ay2 < iH) && (az2 < iD);
            if (!inside) continue;
            float aarea = f_area(ax1, ay1, ax2, ay2, az1, az2);
#pragma unroll
            for (int k2 = 0; k2 < 5; k2++) {
                float ov = f_ov(ax1, ay1, ax2, ay2, az1, az2, aarea, sgt + (tile * 5 + k2) * 7);
                vmax[k2] = fmaxf(vmax[k2], ov);
            }
        }
#pragma unroll
        for (int k2 = 0; k2 < 5; k2++) {
            float v = vmax[k2];
#pragma unroll
            for (int off = 16; off; off >>= 1) v = fmaxf(v, __shfl_xor_sync(0xFFFFFFFFu, v, off));
            if (lane == 0 && v > 0.0f) atomicMax(&smax[tile * 5 + k2], __float_as_int(v));
        }
    }
    __syncthreads();
    if (threadIdx.x < NK) {
        int m = smax[threadIdx.x];
        if (m > 0) atomicMax(&g_gtmax[b * NK + threadIdx.x], m);
    }
}

// ================= passB: labels, argmax, hist, counts ===========================
__global__ void __launch_bounds__(256, 3) k_passB(const float* __restrict__ gt,
                                                  const float* __restrict__ im_info,
                                                  const float* __restrict__ anchors,
                                                  const float* __restrict__ rfg,
                                                  const float* __restrict__ rbg) {
    int b    = blockIdx.x / BPB;
    int base = (blockIdx.x % BPB) * 2048;
    __shared__ float sgt[NK * 7];
    __shared__ float sgm[NK];
    __shared__ float sanch[NA * 6];
    __shared__ int   scnt[2];
    build_sgt(sgt, gt, b);
    if (threadIdx.x < NK) {
        float gm = __int_as_float(g_gtmax[b * NK + threadIdx.x]);
        sgm[threadIdx.x] = (gm == 0.0f) ? 1e-5f : gm;
    }
    if (threadIdx.x < NA * 6) sanch[threadIdx.x] = anchors[threadIdx.x];
    if (threadIdx.x < 2) scnt[threadIdx.x] = 0;
    __syncthreads();
    const float iH = im_info[0], iW = im_info[1], iD = im_info[2];
    const int lane = threadIdx.x & 31;

#pragma unroll 1
    for (int t = 0; t < 8; t++) {
        int i = base + t * 256 + threadIdx.x;
        int e = b * TOTAL + i;
        int a = i % NA; int q = i / NA;
        int d = q % ND; q /= ND;
        int w = q % NW; int h = q / NW;
        float shx = w * 16.0f, shy = h * 16.0f, shz = d * 16.0f;
        const float* an = sanch + a * 6;
        float ax1 = an[0] + shx, ay1 = an[1] + shy;
        float ax2 = an[2] + shx, ay2 = an[3] + shy;
        float az1 = an[4] + shz, az2 = an[5] + shz;
        bool inside = (ax1 >= 0.0f) && (ay1 >= 0.0f) && (az1 >= 0.0f) &&
                      (ax2 < iW) && (ay2 < iH) && (az2 < iD);
        signed char lab = -1;
        unsigned char am = 0;
        if (inside) {
            float aarea = f_area(ax1, ay1, ax2, ay2, az1, az2);
            float best = -1.0f;
            int bi = 0;
            bool tie = false;
#pragma unroll
            for (int k = 0; k < NK; k++) {
                float ov = f_ov(ax1, ay1, ax2, ay2, az1, az2, aarea, sgt + k * 7);
                if (ov > best) { best = ov; bi = k; }
                if (ov == sgm[k]) tie = true;
            }
            lab = (tie || best >= 0.7f) ? 1 : ((best < 0.3f) ? 0 : -1);
            am = (unsigned char)bi;
        }
        g_label[e] = lab;
        g_amax[e]  = am;

        unsigned b1 = __ballot_sync(0xFFFFFFFFu, lab == 1);
        unsigned b0 = __ballot_sync(0xFFFFFFFFu, lab == 0);
        if (lane == 0) {
            if (b1) atomicAdd(&scnt[0], __popc(b1));
            if (b0) atomicAdd(&scnt[1], __popc(b0));
        }
        if (lab == 1) {
            unsigned bin = __float_as_uint(rfg[e]) >> 16;
            atomicAdd(&g_hist[(b * 2) * NBINS + bin], 1u);
        } else if (lab == 0) {
            unsigned bin = __float_as_uint(rbg[e]) >> 16;
            atomicAdd(&g_hist[(b * 2 + 1) * NBINS + bin], 1u);
        }
    }
    __syncthreads();
    if (threadIdx.x < 2 && scnt[threadIdx.x]) atomicAdd(&g_cnt[b * 2 + threadIdx.x], scnt[threadIdx.x]);
}

// ================= upd0: chunk sums + last-block bin resolve =====================
__global__ void __launch_bounds__(256) k_upd0() {
    int grp   = blockIdx.x >> 4;
    int chunk = blockIdx.x & 15;
    int lane = threadIdx.x & 31, wid = threadIdx.x >> 5;
    const uint4* hp = (const uint4*)(g_hist + grp * NBINS + chunk * 4096);
    unsigned s = 0;
#pragma unroll
    for (int j = 0; j < 4; j++) {
        uint4 v = hp[j * 256 + threadIdx.x];
        s += v.x + v.y + v.z + v.w;
    }
#pragma unroll
    for (int off = 16; off; off >>= 1) s += __shfl_xor_sync(0xFFFFFFFFu, s, off);
    __shared__ unsigned wsum[8];
    __shared__ int slast;
    if (lane == 0) wsum[wid] = s;
    __syncthreads();
    if (threadIdx.x == 0) {
        unsigned tot = 0;
#pragma unroll
        for (int i = 0; i < 8; i++) tot += wsum[i];
        g_csum[grp * 16 + chunk] = tot;
        __threadfence();
        int o = atomicAdd(&g_done_u, 1);
        slast = (o == 63) ? 1 : 0;
    }
    __syncthreads();
    if (!slast) return;

    __shared__ unsigned sb[4096];
    for (int g2 = 0; g2 < 4; g2++) {
        int m0;
        if ((g2 & 1) == 0) m0 = NUMFG;
        else { int fgc = g_cnt[g2 - 1]; int kept = (fgc < NUMFG) ? fgc : NUMFG; m0 = RPNB - kept; }
        if (g2 == 3 && threadIdx.x == 0) {
            int fg1 = g_cnt[2]; if (fg1 > NUMFG) fg1 = NUMFG;
            int cap = RPNB - fg1;
            int bg1 = g_cnt[3]; if (bg1 > cap) bg1 = cap;
            int ne = fg1 + bg1;
            g_wval = 1.0f / (float)(ne > 0 ? ne : 1);
        }
        unsigned cs[16];
        unsigned total = 0;
#pragma unroll
        for (int c = 0; c < 16; c++) { cs[c] = g_csum[g2 * 16 + c]; total += cs[c]; }
        if ((unsigned)m0 >= total) {
            if (threadIdx.x == 0) { g_keep[g2] = 1; g_thresh[g2] = 0ULL; }
            continue;
        }
        int cstar = 0; unsigned acc = 0;
        for (int c = 15; c >= 0; c--) {
            if (acc + cs[c] >= (unsigned)m0) { cstar = c; break; }
            acc += cs[c];
        }
        int m_rem = m0 - (int)acc;
        const unsigned* hb = g_hist + g2 * NBINS + cstar * 4096;
        for (int i = threadIdx.x; i < 4096; i += 256) sb[i] = hb[i];
        __syncthreads();
        if (threadIdx.x < 32) {
            unsigned accw = 0;
            for (int basei = 4095; basei >= 31; basei -= 32) {
                unsigned v = sb[basei - lane];
                unsigned inc = v;
#pragma unroll
                for (int off = 1; off < 32; off <<= 1) {
                    unsigned u = __shfl_up_sync(0xFFFFFFFFu, inc, off);
                    if (lane >= off) inc += u;
                }
                unsigned tot32 = __shfl_sync(0xFFFFFFFFu, inc, 31);
                if (accw + tot32 >= (unsigned)m_rem) {
                    unsigned incl = accw + inc;
                    unsigned excl = incl - v;
                    if (excl < (unsigned)m_rem && (unsigned)m_rem <= incl) {
                        g_bin[g2] = (unsigned)(cstar * 4096 + basei - lane);
                        g_m[g2]   = m_rem - (int)excl;
                    }
                    break;
                }
                accw += tot32;
            }
        }
        __syncthreads();
    }
}

// ================= collect: gather keys in the threshold bin =====================
__global__ void __launch_bounds__(256) k_collect(const float* __restrict__ rfg,
                                                 const float* __restrict__ rbg) {
    int e = blockIdx.x * 256 + threadIdx.x;
    int lab = g_label[e];
    if (lab < 0) return;
    int b = (e >= TOTAL) ? 1 : 0;
    unsigned i = (unsigned)(e - b * TOTAL);
    int grp = b * 2 + (lab == 0 ? 1 : 0);
    if (g_keep[grp]) return;
    float rv = (lab == 1) ? rfg[e] : rbg[e];
    unsigned rb = __float_as_uint(rv);
    if ((rb >> 16) != g_bin[grp]) return;
    unsigned long long key = ((unsigned long long)rb << 32) | (unsigned)(~i);
    int pos = atomicAdd(&g_ncand[grp], 1);
    if (pos < CAP) g_cand[grp * CAP + pos] = key;
}

// ================= finish: exact m-th largest within the bin =====================
__global__ void __launch_bounds__(256) k_finish() {
    int grp = blockIdx.x;
    if (g_keep[grp]) return;
    __shared__ unsigned long long sk[CAP];
    int n = g_ncand[grp];
    if (n > CAP) n = CAP;
    int m = g_m[grp];
    for (int i = threadIdx.x; i < n; i += 256) sk[i] = g_cand[grp * CAP + i];
    __syncthreads();
    for (int i = threadIdx.x; i < n; i += 256) {
        unsigned long long k = sk[i];
        int cg = 0;
        for (int j = 0; j < n; j++) cg += (sk[j] > k) ? 1 : 0;
        if (cg == m - 1) g_thresh[grp] = k;
    }
}

// ================= passD: outputs + state reset for next replay ==================
__global__ void __launch_bounds__(256) k_passD(const float* __restrict__ gt,
                                               const float* __restrict__ im_info,
                                               const float* __restrict__ anchors,
                                               const float* __restrict__ rfg,
                                               const float* __restrict__ rbg,
                                               float* __restrict__ out) {
    int tid = blockIdx.x * 256 + threadIdx.x;
    int idx = tid * 4;
    int d0 = idx % ND; int q = idx / ND;
    int w = q % NW; q /= NW;
    int h = q % NH; q /= NH;
    int a = q % NA; int b = q / NA;
    int pix0 = (h * NW + w) * ND + d0;

    __shared__ float sanch[NA * 6];
    __shared__ float sder[NA * 9];
    __shared__ float sgtd[NB * NK * 6];
    __shared__ unsigned long long sth[4];
    if (threadIdx.x < NA * 6) sanch[threadIdx.x] = anchors[threadIdx.x];
    if (threadIdx.x < 4) sth[threadIdx.x] = g_thresh[threadIdx.x];
    if (threadIdx.x >= 128 && threadIdx.x < 128 + NA) {
        int aa = threadIdx.x - 128;
        const float* an = anchors + aa * 6;
        float ew = an[2] - an[0] + 1.0f;
        float eh = an[3] - an[1] + 1.0f;
        float ed = an[5] - an[4] + 1.0f;
        float* o = sder + aa * 9;
        o[0] = an[0] + 0.5f * (ew - 1.0f);
        o[1] = an[1] + 0.5f * (eh - 1.0f);
        o[2] = an[4] + 0.5f * (ed - 1.0f);
        o[3] = 1.0f / ew; o[4] = 1.0f / eh; o[5] = 1.0f / ed;
        o[6] = logf(ew); o[7] = logf(eh); o[8] = logf(ed);
    }
    if (threadIdx.x >= 160 && threadIdx.x < 160 + NB * NK) {
        int j = threadIdx.x - 160;
        const float* g = gt + j * 7;
        float gw = g[2] - g[0] + 1.0f, gh = g[3] - g[1] + 1.0f, gd = g[5] - g[4] + 1.0f;
        float* o = sgtd + j * 6;
        o[0] = g[0] + 0.5f * (gw - 1.0f);
        o[1] = g[1] + 0.5f * (gh - 1.0f);
        o[2] = g[4] + 0.5f * (gd - 1.0f);
        o[3] = logf(gw); o[4] = logf(gh); o[5] = logf(gd);
    }
    __syncthreads();

    const float iH = im_info[0], iW = im_info[1], iD = im_info[2];
    const float* an = sanch + a * 6;
    const float* ad = sder + a * 9;
    float shx = w * 16.0f, shy = h * 16.0f;
    float ax1 = an[0] + shx, ay1 = an[1] + shy;
    float ax2 = an[2] + shx, ay2 = an[3] + shy;
    bool inxy = (ax1 >= 0.0f) && (ay1 >= 0.0f) && (ax2 < iW) && (ay2 < iH);
    float wv = g_wval;

    float lb[4], ivv[4], ovv[4];
    float T[6][4];
#pragma unroll
    for (int j = 0; j < 4; j++) {
        float shz = (float)(d0 + j) * 16.0f;
        float az1 = an[4] + shz, az2 = an[5] + shz;
        bool inside = inxy && (az1 >= 0.0f) && (az2 < iD);
        int ia = (pix0 + j) * NA + a;
        int e  = b * TOTAL + ia;
        int lab = (int)g_label[e];
        if (lab >= 0) {
            int grp = b * 2 + (lab == 0 ? 1 : 0);
            float rv = (lab == 1) ? rfg[e] : rbg[e];
            unsigned long long key = ((unsigned long long)__float_as_uint(rv) << 32) | (unsigned)(~(unsigned)ia);
            if (key < sth[grp]) lab = -1;
        }
        float t0 = 0.0f, t1 = 0.0f, t2 = 0.0f, t3 = 0.0f, t4 = 0.0f, t5 = 0.0f;
        if (inside) {
            int am = (int)g_amax[e];
            const float* gd = sgtd + (b * NK + am) * 6;
            t0 = (gd[0] - ad[0] - shx) * ad[3];
            t1 = (gd[1] - ad[1] - shy) * ad[4];
            t2 = (gd[2] - ad[2] - shz) * ad[5];
            t3 = gd[3] - ad[6];
            t4 = gd[4] - ad[7];
            t5 = gd[5] - ad[8];
        }
        T[0][j] = t0; T[1][j] = t1; T[2][j] = t2;
        T[3][j] = t3; T[4][j] = t4; T[5][j] = t5;
        lb[j]  = (float)lab;
        ivv[j] = (lab == 1) ? 1.0f : 0.0f;
        ovv[j] = (lab >= 0) ? wv : 0.0f;
    }

    *(float4*)(out + idx) = make_float4(lb[0], lb[1], lb[2], lb[3]);
    long long base = (long long)(b * 54 + a * 6) * HWD + pix0;
    float* bt = out + OFF_BT + base;
#pragma unroll
    for (int c = 0; c < 6; c++)
        *(float4*)(bt + c * HWD) = make_float4(T[c][0], T[c][1], T[c][2], T[c][3]);
    float* iwp = out + OFF_IW + base;
    float* owp = out + OFF_OW + base;
    float4 iv = make_float4(ivv[0], ivv[1], ivv[2], ivv[3]);
    float4 ov = make_float4(ovv[0], ovv[1], ovv[2], ovv[3]);
#pragma unroll
    for (int c = 0; c < 6; c++) {
        *(float4*)(iwp + c * HWD) = iv;
        *(float4*)(owp + c * HWD) = ov;
    }

    // ---- state reset for the next graph replay (block 0; values unused below) ----
    if (blockIdx.x == 0) {
        int t = threadIdx.x;
        if (t < NB * NK) g_gtmax[t] = 0;
        if (t >= 64 && t < 68)  g_cnt[t - 64] = 0;
        if (t >= 72 && t < 76)  g_ncand[t - 72] = 0;
        if (t >= 80 && t < 84)  g_keep[t - 80] = 0;
        if (t == 90) g_done_u = 0;
    }
}

// ---------------- launch ----------------
extern "C" void kernel_launch(void* const* d_in, const int* in_sizes, int n_in,
                              void* d_out, int out_size) {
    const float* gt      = (const float*)d_in[1];
    const float* im_info = (const float*)d_in[2];
    const float* anchors = (const float*)d_in[4];
    const float* rfg     = (const float*)d_in[5];
    const float* rbg     = (const float*)d_in[6];
    float* out           = (float*)d_out;

    k_passA<<<NB * BPB, 256>>>(gt, im_info, anchors);
    k_passB<<<NB * BPB, 256>>>(gt, im_info, anchors, rfg, rbg);
    k_upd0<<<64, 256>>>();
    k_collect<<<(NB * TOTAL) / 256, 256>>>(rfg, rbg);
    k_finish<<<4, 256>>>();
    k_passD<<<OUTTOT / 4 / 256, 256>>>(gt, im_info, anchors, rfg, rbg, out);
}